// round 2
// baseline (speedup 1.0000x reference)
#include <cuda_runtime.h>

#define N_NODES 100000
#define N_EDGES 640000
#define FEAT 128
#define HID 256
#define NCLS 10

// Persistent scratch (re-initialized every launch before use).
__device__ __align__(16) float g_agg1[N_NODES * FEAT];
__device__ __align__(16) float g_h1[N_NODES * HID];
__device__ __align__(16) float g_h[N_NODES * HID];
__device__ __align__(16) float g_agg2[N_NODES * HID];
__device__ __align__(16) float g_z[N_NODES * HID];
__device__ int g_src[N_EDGES];
__device__ int g_dst[N_EDGES];
__device__ int g_is64;

// ---------------------------------------------------------------------------
// Edge-index dtype sniffing + conversion.
// JAX demotes int64->int32 when x64 is disabled; handle both layouts.
// For genuine int64 (values < 2^31, non-negative) every odd 32-bit word is 0.
// For int32 random indices in [0,1e5), 256 consecutive odd words all being
// zero has probability ~1e-1280. Deterministic, graph-capturable.
// ---------------------------------------------------------------------------
__global__ void detect_kernel(const unsigned int* __restrict__ w) {
    if (threadIdx.x == 0 && blockIdx.x == 0) {
        int is64 = 1;
        for (int i = 0; i < 256; i++) {
            if (w[2 * i + 1] != 0u) { is64 = 0; break; }
        }
        g_is64 = is64;
    }
}

__global__ void convert_kernel(const void* __restrict__ ei) {
    int e = blockIdx.x * 256 + threadIdx.x;
    if (e >= N_EDGES) return;
    int s, d;
    if (g_is64) {
        const long long* p = (const long long*)ei;
        s = (int)p[e];
        d = (int)p[N_EDGES + e];
    } else {
        const int* p = (const int*)ei;
        s = p[e];
        d = p[N_EDGES + e];
    }
    // clamp: interpretation errors become rel_err, never an IMA
    s = min(max(s, 0), N_NODES - 1);
    d = min(max(d, 0), N_NODES - 1);
    g_src[e] = s;
    g_dst[e] = d;
}

// ---------------------------------------------------------------------------
// packed f32x2 helpers (FFMA2: full-rate fp32 on Blackwell)
// ---------------------------------------------------------------------------
__device__ __forceinline__ unsigned long long dup2(float x) {
    unsigned long long r;
    unsigned int xi = __float_as_uint(x);
    asm("mov.b64 %0, {%1, %1};" : "=l"(r) : "r"(xi));
    return r;
}
__device__ __forceinline__ void ffma2(unsigned long long& d,
                                      unsigned long long a,
                                      unsigned long long b) {
    asm("fma.rn.f32x2 %0, %1, %2, %0;" : "+l"(d) : "l"(a), "l"(b));
}

// ---------------------------------------------------------------------------
// float4 copy (self-loop init: agg = x / agg = h)
// ---------------------------------------------------------------------------
__global__ void copy4_kernel(float4* __restrict__ dst,
                             const float4* __restrict__ src, int n4) {
    int i = blockIdx.x * 256 + threadIdx.x;
    if (i < n4) dst[i] = src[i];
}

// ---------------------------------------------------------------------------
// Edge aggregation: agg[dst] += x[src], vectorized float4 atomics.
// CH consecutive threads handle one edge (coalesced gather/scatter; index
// loads broadcast within the group).
// ---------------------------------------------------------------------------
template <int D>
__global__ void edge_agg_kernel(const float* __restrict__ x,
                                float* __restrict__ agg) {
    const int CH = D / 4;
    int i = blockIdx.x * 256 + threadIdx.x;
    if (i >= N_EDGES * CH) return;
    int e = i / CH;
    int c = i - e * CH;
    int s = g_src[e];
    int d = g_dst[e];
    const float4 v =
        *reinterpret_cast<const float4*>(x + (size_t)s * D + (size_t)c * 4);
    atomicAdd(reinterpret_cast<float4*>(agg + (size_t)d * D + (size_t)c * 4), v);
}

// ---------------------------------------------------------------------------
// Tiled fp32 GEMM: C[M,256] = act(A[M,K] @ B[K,256] + bias)
// Block tile 128x128, BK=16, 256 threads, 8x8 microtile, f32x2 accumulators.
// ---------------------------------------------------------------------------
__global__ __launch_bounds__(256, 2)
void gemm_n256(const float* __restrict__ A, const float* __restrict__ Bw,
               const float* __restrict__ bias, float* __restrict__ C,
               int M, int K, int do_relu) {
    __shared__ __align__(16) float As[2][16][132];  // [k][m], +4 pad
    __shared__ __align__(16) float Bs[2][16][128];  // [k][n]

    const int t = threadIdx.x;
    const int bm = blockIdx.x * 128;
    const int bn = blockIdx.y * 128;

    const int ar = t >> 2;          // A row within tile: 0..63 (and +64)
    const int ac = (t & 3) * 4;     // A col group: 0,4,8,12
    const int bk = t >> 5;          // B k-row: 0..7 (and +8)
    const int bnc = (t & 31) * 4;   // B col: 0..124

    const bool am0 = (bm + ar) < M;
    const bool am1 = (bm + ar + 64) < M;
    const float* Ap0 = A + (size_t)(bm + ar) * K + ac;
    const float* Ap1 = A + (size_t)(bm + ar + 64) * K + ac;
    const float* Bp0 = Bw + (size_t)bk * HID + bn + bnc;
    const float* Bp1 = Bw + (size_t)(bk + 8) * HID + bn + bnc;

    unsigned long long acc[4][8];
#pragma unroll
    for (int p = 0; p < 4; p++)
#pragma unroll
        for (int j = 0; j < 8; j++) acc[p][j] = 0ULL;

    const float4 z4 = make_float4(0.f, 0.f, 0.f, 0.f);
    float4 fa0, fa1, fb0, fb1;

    // prologue: tile 0
    fa0 = am0 ? *reinterpret_cast<const float4*>(Ap0) : z4;
    fa1 = am1 ? *reinterpret_cast<const float4*>(Ap1) : z4;
    fb0 = *reinterpret_cast<const float4*>(Bp0);
    fb1 = *reinterpret_cast<const float4*>(Bp1);
    As[0][ac + 0][ar] = fa0.x; As[0][ac + 1][ar] = fa0.y;
    As[0][ac + 2][ar] = fa0.z; As[0][ac + 3][ar] = fa0.w;
    As[0][ac + 0][ar + 64] = fa1.x; As[0][ac + 1][ar + 64] = fa1.y;
    As[0][ac + 2][ar + 64] = fa1.z; As[0][ac + 3][ar + 64] = fa1.w;
    *reinterpret_cast<float4*>(&Bs[0][bk][bnc]) = fb0;
    *reinterpret_cast<float4*>(&Bs[0][bk + 8][bnc]) = fb1;
    __syncthreads();

    const int tm = (t & 15) * 8;   // microtile rows
    const int tn = (t >> 4) * 8;   // microtile cols
    const int nk = K >> 4;

    for (int kt = 0; kt < nk; kt++) {
        if (kt + 1 < nk) {  // prefetch next k-chunk into registers
            const int k0 = (kt + 1) << 4;
            fa0 = am0 ? *reinterpret_cast<const float4*>(Ap0 + k0) : z4;
            fa1 = am1 ? *reinterpret_cast<const float4*>(Ap1 + k0) : z4;
            fb0 = *reinterpret_cast<const float4*>(Bp0 + (size_t)k0 * HID);
            fb1 = *reinterpret_cast<const float4*>(Bp1 + (size_t)k0 * HID);
        }
        const int buf = kt & 1;
#pragma unroll
        for (int k = 0; k < 16; k++) {
            ulonglong2 av0 =
                *reinterpret_cast<const ulonglong2*>(&As[buf][k][tm]);
            ulonglong2 av1 =
                *reinterpret_cast<const ulonglong2*>(&As[buf][k][tm + 4]);
            float4 w0 = *reinterpret_cast<const float4*>(&Bs[buf][k][tn]);
            float4 w1 = *reinterpret_cast<const float4*>(&Bs[buf][k][tn + 4]);
            const unsigned long long ap0 = av0.x, ap1 = av0.y;
            const unsigned long long ap2 = av1.x, ap3 = av1.y;
            const float wv[8] = {w0.x, w0.y, w0.z, w0.w,
                                 w1.x, w1.y, w1.z, w1.w};
#pragma unroll
            for (int j = 0; j < 8; j++) {
                unsigned long long bd = dup2(wv[j]);
                ffma2(acc[0][j], ap0, bd);
                ffma2(acc[1][j], ap1, bd);
                ffma2(acc[2][j], ap2, bd);
                ffma2(acc[3][j], ap3, bd);
            }
        }
        if (kt + 1 < nk) {
            const int nb = 1 - buf;
            As[nb][ac + 0][ar] = fa0.x; As[nb][ac + 1][ar] = fa0.y;
            As[nb][ac + 2][ar] = fa0.z; As[nb][ac + 3][ar] = fa0.w;
            As[nb][ac + 0][ar + 64] = fa1.x; As[nb][ac + 1][ar + 64] = fa1.y;
            As[nb][ac + 2][ar + 64] = fa1.z; As[nb][ac + 3][ar + 64] = fa1.w;
            *reinterpret_cast<float4*>(&Bs[nb][bk][bnc]) = fb0;
            *reinterpret_cast<float4*>(&Bs[nb][bk + 8][bnc]) = fb1;
            __syncthreads();
        }
    }

    // epilogue: bias + optional relu, unpack row pairs, float4 stores
    float bz[8];
#pragma unroll
    for (int j = 0; j < 8; j++) bz[j] = bias[bn + tn + j];

#pragma unroll
    for (int p = 0; p < 4; p++) {
        float lo[8], hi[8];
#pragma unroll
        for (int j = 0; j < 8; j++) {
            unsigned long long u = acc[p][j];
            float vx = __uint_as_float((unsigned int)(u & 0xffffffffULL));
            float vy = __uint_as_float((unsigned int)(u >> 32));
            vx += bz[j];
            vy += bz[j];
            if (do_relu) { vx = fmaxf(vx, 0.f); vy = fmaxf(vy, 0.f); }
            lo[j] = vx;
            hi[j] = vy;
        }
        int r0 = bm + tm + 2 * p;
        if (r0 < M) {
            float4* cp =
                reinterpret_cast<float4*>(C + (size_t)r0 * HID + bn + tn);
            cp[0] = make_float4(lo[0], lo[1], lo[2], lo[3]);
            cp[1] = make_float4(lo[4], lo[5], lo[6], lo[7]);
        }
        if (r0 + 1 < M) {
            float4* cp = reinterpret_cast<float4*>(C + (size_t)(r0 + 1) * HID +
                                                   bn + tn);
            cp[0] = make_float4(hi[0], hi[1], hi[2], hi[3]);
            cp[1] = make_float4(hi[4], hi[5], hi[6], hi[7]);
        }
    }
}

// ---------------------------------------------------------------------------
// Final GEMM: out[M,10] = Z[M,256] @ W[256,10] + b. Warp per row,
// W transposed into smem for conflict-free access.
// ---------------------------------------------------------------------------
__global__ void gemm_out_k(const float* __restrict__ Z,
                           const float* __restrict__ W,
                           const float* __restrict__ bias,
                           float* __restrict__ out) {
    __shared__ float Ws[NCLS][HID];
    __shared__ float bs[NCLS];
    const int t = threadIdx.x;
    for (int i = t; i < HID * NCLS; i += 256) {
        int k = i / NCLS;
        int c = i - k * NCLS;
        Ws[c][k] = W[i];
    }
    if (t < NCLS) bs[t] = bias[t];
    __syncthreads();

    const int lane = t & 31;
    const int row = blockIdx.x * 8 + (t >> 5);
    if (row >= N_NODES) return;

    const float* zr = Z + (size_t)row * HID;
    float zv[8];
#pragma unroll
    for (int i = 0; i < 8; i++) zv[i] = zr[i * 32 + lane];

#pragma unroll
    for (int c = 0; c < NCLS; c++) {
        float s = 0.f;
#pragma unroll
        for (int i = 0; i < 8; i++) s += zv[i] * Ws[c][i * 32 + lane];
#pragma unroll
        for (int o = 16; o > 0; o >>= 1) s += __shfl_xor_sync(0xffffffffu, s, o);
        if (lane == 0) out[row * NCLS + c] = s + bs[c];
    }
}

// ---------------------------------------------------------------------------
// Launch sequence (default stream; graph-capturable, alloc-free)
// ---------------------------------------------------------------------------
extern "C" void kernel_launch(void* const* d_in, const int* in_sizes, int n_in,
                              void* d_out, int out_size) {
    (void)in_sizes; (void)n_in; (void)out_size;
    const float* x = (const float*)d_in[0];
    const void* ei = d_in[1];
    const float* W1a = (const float*)d_in[2];
    const float* b1a = (const float*)d_in[3];
    const float* W1b = (const float*)d_in[4];
    const float* b1b = (const float*)d_in[5];
    const float* W2a = (const float*)d_in[6];
    const float* b2a = (const float*)d_in[7];
    const float* W2b = (const float*)d_in[8];
    const float* b2b = (const float*)d_in[9];
    float* out = (float*)d_out;

    float *agg1, *h1, *h, *agg2, *z;
    cudaGetSymbolAddress((void**)&agg1, g_agg1);
    cudaGetSymbolAddress((void**)&h1, g_h1);
    cudaGetSymbolAddress((void**)&h, g_h);
    cudaGetSymbolAddress((void**)&agg2, g_agg2);
    cudaGetSymbolAddress((void**)&z, g_z);

    // index dtype sniff + conversion to int32 scratch
    detect_kernel<<<1, 32>>>((const unsigned int*)ei);
    convert_kernel<<<(N_EDGES + 255) / 256, 256>>>(ei);

    const dim3 ggrid((N_NODES + 127) / 128, 2);

    // ---- layer 1 ----
    {
        int n4 = N_NODES * FEAT / 4;
        copy4_kernel<<<(n4 + 255) / 256, 256>>>((float4*)agg1,
                                                (const float4*)x, n4);
        int nt = N_EDGES * (FEAT / 4);
        edge_agg_kernel<FEAT><<<(nt + 255) / 256, 256>>>(x, agg1);
        gemm_n256<<<ggrid, 256>>>(agg1, W1a, b1a, h1, N_NODES, FEAT, 1);
        gemm_n256<<<ggrid, 256>>>(h1, W1b, b1b, h, N_NODES, HID, 1);
    }
    // ---- layer 2 ----
    {
        int n4 = N_NODES * HID / 4;
        copy4_kernel<<<(n4 + 255) / 256, 256>>>((float4*)agg2,
                                                (const float4*)h, n4);
        int nt = N_EDGES * (HID / 4);
        edge_agg_kernel<HID><<<(nt + 255) / 256, 256>>>(h, agg2);
        gemm_n256<<<ggrid, 256>>>(agg2, W2a, b2a, z, N_NODES, HID, 1);
        gemm_out_k<<<(N_NODES + 7) / 8, 256>>>(z, W2b, b2b, out);
    }
}

// round 6
// speedup vs baseline: 1.5519x; 1.5519x over previous
#include <cuda_runtime.h>
#include <cuda_bf16.h>
#include <cstdint>

#define N_NODES 100000
#define N_EDGES 640000
#define FEAT 128
#define HID 256
#define NCLS 10

// ---------------------------------------------------------------------------
// Persistent scratch (re-initialized every launch before use).
// ---------------------------------------------------------------------------
__device__ __align__(16) float g_agg1[N_NODES * FEAT];
__device__ __align__(16) float g_h1[N_NODES * HID];
__device__ __align__(16) float g_h[N_NODES * HID];
__device__ __align__(16) float g_agg2[N_NODES * HID];
__device__ __align__(16) float g_z[N_NODES * HID];
__device__ int g_src[N_EDGES];
__device__ int g_dst[N_EDGES];
// prepped weights, bf16: [chunk][plane(hi,lo)][k(32)][n(256)]
__device__ __align__(16) __nv_bfloat16 g_wp1[4 * 2 * 32 * 256];  // W1a K=128
__device__ __align__(16) __nv_bfloat16 g_wp2[8 * 2 * 32 * 256];  // W1b K=256
__device__ __align__(16) __nv_bfloat16 g_wp3[8 * 2 * 32 * 256];  // W2a K=256

// ---------------------------------------------------------------------------
// mma.sync helpers (legacy tensor-core path; valid at compute_100)
// ---------------------------------------------------------------------------
#define LDSM4(r, a)                                                           \
    asm volatile("ldmatrix.sync.aligned.m8n8.x4.shared.b16 {%0,%1,%2,%3}, [%4];" \
                 : "=r"((r)[0]), "=r"((r)[1]), "=r"((r)[2]), "=r"((r)[3])     \
                 : "r"(a))
#define LDSM2T(r, a)                                                          \
    asm volatile("ldmatrix.sync.aligned.m8n8.x2.trans.shared.b16 {%0,%1}, [%2];" \
                 : "=r"((r)[0]), "=r"((r)[1])                                 \
                 : "r"(a))
#define MMA16816(c, A, B)                                                     \
    asm volatile(                                                             \
        "mma.sync.aligned.m16n8k16.row.col.f32.bf16.bf16.f32 "                \
        "{%0,%1,%2,%3},{%4,%5,%6,%7},{%8,%9},{%0,%1,%2,%3};"                  \
        : "+f"((c)[0]), "+f"((c)[1]), "+f"((c)[2]), "+f"((c)[3])              \
        : "r"((A)[0]), "r"((A)[1]), "r"((A)[2]), "r"((A)[3]), "r"((B)[0]),    \
          "r"((B)[1]))
#define CP_ASYNC16(dst, src)                                                  \
    asm volatile("cp.async.cg.shared.global [%0], [%1], 16;" ::"r"(dst),      \
                 "l"(src) : "memory")
#define CP_COMMIT() asm volatile("cp.async.commit_group;" ::: "memory")
#define CP_WAIT0() asm volatile("cp.async.wait_group 0;" ::: "memory")

__device__ __forceinline__ uint32_t smem_u32(const void* p) {
    uint32_t a;
    asm("{ .reg .u64 t; cvta.to.shared.u64 t, %1; cvt.u32.u64 %0, t; }"
        : "=r"(a) : "l"(p));
    return a;
}
// pack two floats to bf16x2 (lo -> low 16 bits)
__device__ __forceinline__ uint32_t pk(float lo, float hi) {
    uint32_t r;
    asm("cvt.rn.bf16x2.f32 %0, %1, %2;" : "=r"(r) : "f"(hi), "f"(lo));
    return r;
}
__device__ __forceinline__ float bfr(float x) {
    return __bfloat162float(__float2bfloat16(x));
}

// ---------------------------------------------------------------------------
// Edge-index conversion with per-block dtype sniff (JAX may demote
// int64->int32). Each block independently derives the dtype from the first
// 256 index slots: a genuine int64 buffer of values in [0, 1e5) has zero in
// every odd 32-bit word; int32 random data cannot (p ~ 1e-1280).
// Deterministic, no global round-trip.
// ---------------------------------------------------------------------------
__global__ void convert_kernel(const void* __restrict__ ei) {
    __shared__ int s_is64;
    if (threadIdx.x == 0) {
        const unsigned int* w = (const unsigned int*)ei;
        int is64 = 1;
        for (int i = 0; i < 256; i++)
            if (w[2 * i + 1] != 0u) { is64 = 0; break; }
        s_is64 = is64;
    }
    __syncthreads();
    int e = blockIdx.x * 256 + threadIdx.x;
    if (e >= N_EDGES) return;
    int s, d;
    if (s_is64) {
        const long long* p = (const long long*)ei;
        s = (int)p[e];
        d = (int)p[N_EDGES + e];
    } else {
        const int* p = (const int*)ei;
        s = p[e];
        d = p[N_EDGES + e];
    }
    s = min(max(s, 0), N_NODES - 1);
    d = min(max(d, 0), N_NODES - 1);
    g_src[e] = s;
    g_dst[e] = d;
}

// ---------------------------------------------------------------------------
// float4 copy (self-loop init)
// ---------------------------------------------------------------------------
__global__ void copy4_kernel(float4* __restrict__ dst,
                             const float4* __restrict__ src, int n4) {
    int i = blockIdx.x * 256 + threadIdx.x;
    if (i < n4) dst[i] = src[i];
}

// ---------------------------------------------------------------------------
// Edge aggregation: agg[dst] += x[src], float4 atomics.
// ---------------------------------------------------------------------------
template <int D>
__global__ void edge_agg_kernel(const float* __restrict__ x,
                                float* __restrict__ agg) {
    const int CH = D / 4;
    int i = blockIdx.x * 256 + threadIdx.x;
    if (i >= N_EDGES * CH) return;
    int e = i / CH;
    int c = i - e * CH;
    int s = g_src[e];
    int d = g_dst[e];
    const float4 v =
        *reinterpret_cast<const float4*>(x + (size_t)s * D + (size_t)c * 4);
    atomicAdd(reinterpret_cast<float4*>(agg + (size_t)d * D + (size_t)c * 4), v);
}

// ---------------------------------------------------------------------------
// Weight prep: W[K,256] fp32 -> bf16 hi/lo planes, layout
// [chunk(K/32)][plane(2)][k(32)][n(256)]
// ---------------------------------------------------------------------------
__global__ void prep_w_kernel(const float* __restrict__ W,
                              __nv_bfloat16* __restrict__ out, int K) {
    int i = blockIdx.x * 256 + threadIdx.x;
    if (i >= K * 256) return;
    int k = i >> 8;
    int n = i & 255;
    float v = W[(size_t)k * 256 + n];
    __nv_bfloat16 hi = __float2bfloat16(v);
    __nv_bfloat16 lo = __float2bfloat16(v - __bfloat162float(hi));
    int chunk = k >> 5, kk = k & 31;
    size_t base = ((size_t)chunk * 2 * 32 + kk) * 256 + n;
    out[base] = hi;                    // plane 0
    out[base + (size_t)32 * 256] = lo; // plane 1
}

// ---------------------------------------------------------------------------
// bf16x3 mma.sync GEMM: C[M,256] = relu(A[M,K] @ W[K,256] + bias)
// CTA 128x128, 512 threads (16 warps, 4x4), warp tile 32x32, BK=32, 2 stages.
// SMEM per stage: A_hi[128][40bf16] | A_lo | B_hi[32][136bf16] | B_lo
// ---------------------------------------------------------------------------
#define A_HI_OFF 0
#define A_LO_OFF 10240
#define B_HI_OFF 20480
#define B_LO_OFF 29184
#define STAGE_BYTES 37888
#define SMEM_MMA_BYTES (2 * STAGE_BYTES)

template <int NC>  // K / 32
__global__ __launch_bounds__(512)
void gemm_mma(const float* __restrict__ A,
              const __nv_bfloat16* __restrict__ wp,
              const float* __restrict__ bias, float* __restrict__ C, int M) {
    extern __shared__ __align__(1024) char smem[];
    const uint32_t sb = smem_u32(smem);
    const int K = NC * 32;
    const int t = threadIdx.x;
    const int lane = t & 31;
    const int warp = t >> 5;
    const int warp_m = warp >> 2;  // 0..3 (32 rows each)
    const int warp_n = warp & 3;   // 0..3 (32 cols each)
    const int bm = blockIdx.x * 128;
    const int bn = blockIdx.y * 128;

    // ---- A fill coords: thread -> (row 0..127, q 0..3 of 8 floats) ----
    const int a_row = t >> 2;
    const int a_q = t & 3;
    const bool rok = (bm + a_row) < M;
    const float* Ag = A + (size_t)(bm + a_row) * K + a_q * 8;
    const uint32_t a_dst = sb + a_row * 80 + a_q * 16;

    // ---- B fill coords (two cp.async per thread, planes hi/lo) ----
    const int b_k = (t >> 4) & 31;
    const int b_seg = t & 15;
    const int b_pl = t >> 9;  // always 0 for t<512; second op uses t+512
    (void)b_pl;

    // ---- ldmatrix per-thread offsets ----
    const int lm_arow = warp_m * 32 + (lane & 7) + ((lane >> 3) & 1) * 8;
    const uint32_t a_lm = sb + lm_arow * 80 + ((lane >> 4) & 1) * 16;
    const uint32_t b_lm = sb + B_HI_OFF + (lane & 15) * 272 + warp_n * 64;

    float acc[2][4][4];
#pragma unroll
    for (int i = 0; i < 2; i++)
#pragma unroll
        for (int j = 0; j < 4; j++)
#pragma unroll
            for (int k = 0; k < 4; k++) acc[i][j][k] = 0.f;

    // ---- helpers ----
    auto fill_B = [&](int c, int stg) {
        const __nv_bfloat16* srcH =
            wp + (((size_t)c * 2 + 0) * 32 + b_k) * 256 + bn + b_seg * 8;
        const __nv_bfloat16* srcL =
            wp + (((size_t)c * 2 + 1) * 32 + b_k) * 256 + bn + b_seg * 8;
        uint32_t dstH =
            sb + stg * STAGE_BYTES + B_HI_OFF + b_k * 272 + b_seg * 16;
        uint32_t dstL =
            sb + stg * STAGE_BYTES + B_LO_OFF + b_k * 272 + b_seg * 16;
        CP_ASYNC16(dstH, (const void*)srcH);
        CP_ASYNC16(dstL, (const void*)srcL);
        CP_COMMIT();
    };
    auto store_A = [&](int stg, float4 v0, float4 v1) {
        uint32_t h0 = pk(v0.x, v0.y), h1 = pk(v0.z, v0.w);
        uint32_t h2 = pk(v1.x, v1.y), h3 = pk(v1.z, v1.w);
        uint32_t l0 = pk(v0.x - bfr(v0.x), v0.y - bfr(v0.y));
        uint32_t l1 = pk(v0.z - bfr(v0.z), v0.w - bfr(v0.w));
        uint32_t l2 = pk(v1.x - bfr(v1.x), v1.y - bfr(v1.y));
        uint32_t l3 = pk(v1.z - bfr(v1.z), v1.w - bfr(v1.w));
        uint32_t d = a_dst + stg * STAGE_BYTES;
        asm volatile("st.shared.v4.b32 [%0], {%1,%2,%3,%4};" ::"r"(d), "r"(h0),
                     "r"(h1), "r"(h2), "r"(h3));
        asm volatile("st.shared.v4.b32 [%0], {%1,%2,%3,%4};" ::"r"(
                         d + A_LO_OFF),
                     "r"(l0), "r"(l1), "r"(l2), "r"(l3));
    };
    auto load_A = [&](int c, float4& v0, float4& v1) {
        if (rok) {
            v0 = *reinterpret_cast<const float4*>(Ag + c * 32);
            v1 = *reinterpret_cast<const float4*>(Ag + c * 32 + 4);
        } else {
            v0 = make_float4(0.f, 0.f, 0.f, 0.f);
            v1 = v0;
        }
    };
    auto compute = [&](int stg) {
        const uint32_t abase = a_lm + stg * STAGE_BYTES;
        const uint32_t bbase = b_lm + stg * STAGE_BYTES;
#pragma unroll
        for (int ks = 0; ks < 2; ks++) {
            uint32_t Ah[2][4], Al[2][4], Bh[4][2], Bl[4][2];
#pragma unroll
            for (int mt = 0; mt < 2; mt++) {
                uint32_t ad = abase + mt * (16 * 80) + ks * 32;
                LDSM4(Ah[mt], ad);
                LDSM4(Al[mt], ad + A_LO_OFF);
            }
#pragma unroll
            for (int nt = 0; nt < 4; nt++) {
                uint32_t bd = bbase + ks * (16 * 272) + nt * 16;
                LDSM2T(Bh[nt], bd);
                LDSM2T(Bl[nt], bd + (B_LO_OFF - B_HI_OFF));
            }
#pragma unroll
            for (int mt = 0; mt < 2; mt++)
#pragma unroll
                for (int nt = 0; nt < 4; nt++) {
                    MMA16816(acc[mt][nt], Ah[mt], Bh[nt]);
                    MMA16816(acc[mt][nt], Al[mt], Bh[nt]);
                    MMA16816(acc[mt][nt], Ah[mt], Bl[nt]);
                }
        }
    };

    // ---- prologue ----
    {
        fill_B(0, 0);
        float4 v0, v1;
        load_A(0, v0, v1);
        store_A(0, v0, v1);
        CP_WAIT0();
        __syncthreads();
    }
    // ---- main loop ----
    for (int c = 0; c < NC; c++) {
        const int s = c & 1;
        const bool nxt = (c + 1 < NC);
        float4 v0, v1;
        if (nxt) {
            fill_B(c + 1, s ^ 1);
            load_A(c + 1, v0, v1);
        }
        compute(s);
        if (nxt) {
            store_A(s ^ 1, v0, v1);
            CP_WAIT0();
            __syncthreads();
        }
    }

    // ---- epilogue: bias + relu, float2 stores ----
#pragma unroll
    for (int mt = 0; mt < 2; mt++) {
        int r0 = bm + warp_m * 32 + mt * 16 + (lane >> 2);
#pragma unroll
        for (int nt = 0; nt < 4; nt++) {
            int col = bn + warp_n * 32 + nt * 8 + (lane & 3) * 2;
            float b0 = bias[col], b1 = bias[col + 1];
            if (r0 < M) {
                float2 o;
                o.x = fmaxf(acc[mt][nt][0] + b0, 0.f);
                o.y = fmaxf(acc[mt][nt][1] + b1, 0.f);
                *reinterpret_cast<float2*>(C + (size_t)r0 * HID + col) = o;
            }
            if (r0 + 8 < M) {
                float2 o;
                o.x = fmaxf(acc[mt][nt][2] + b0, 0.f);
                o.y = fmaxf(acc[mt][nt][3] + b1, 0.f);
                *reinterpret_cast<float2*>(C + (size_t)(r0 + 8) * HID + col) = o;
            }
        }
    }
}

// ---------------------------------------------------------------------------
// Final GEMM: out[M,10] = Z[M,256] @ W[256,10] + b.
// ---------------------------------------------------------------------------
__global__ void gemm_out_k(const float* __restrict__ Z,
                           const float* __restrict__ W,
                           const float* __restrict__ bias,
                           float* __restrict__ out) {
    __shared__ float Ws[NCLS][HID];
    __shared__ float bs[NCLS];
    const int t = threadIdx.x;
    for (int i = t; i < HID * NCLS; i += 256) {
        int k = i / NCLS;
        int c = i - k * NCLS;
        Ws[c][k] = W[i];
    }
    if (t < NCLS) bs[t] = bias[t];
    __syncthreads();

    const int lane = t & 31;
    const int row = blockIdx.x * 8 + (t >> 5);
    if (row >= N_NODES) return;

    const float* zr = Z + (size_t)row * HID;
    float zv[8];
#pragma unroll
    for (int i = 0; i < 8; i++) zv[i] = zr[i * 32 + lane];

#pragma unroll
    for (int c = 0; c < NCLS; c++) {
        float s = 0.f;
#pragma unroll
        for (int i = 0; i < 8; i++) s += zv[i] * Ws[c][i * 32 + lane];
#pragma unroll
        for (int o = 16; o > 0; o >>= 1) s += __shfl_xor_sync(0xffffffffu, s, o);
        if (lane == 0) out[row * NCLS + c] = s + bs[c];
    }
}

// ---------------------------------------------------------------------------
// Launch sequence (default stream; graph-capturable, alloc-free)
// ---------------------------------------------------------------------------
extern "C" void kernel_launch(void* const* d_in, const int* in_sizes, int n_in,
                              void* d_out, int out_size) {
    (void)in_sizes; (void)n_in; (void)out_size;
    const float* x = (const float*)d_in[0];
    const void* ei = d_in[1];
    const float* W1a = (const float*)d_in[2];
    const float* b1a = (const float*)d_in[3];
    const float* W1b = (const float*)d_in[4];
    const float* b1b = (const float*)d_in[5];
    const float* W2a = (const float*)d_in[6];
    const float* b2a = (const float*)d_in[7];
    const float* W2b = (const float*)d_in[8];
    const float* b2b = (const float*)d_in[9];
    float* out = (float*)d_out;

    float *agg1, *h1, *h, *agg2, *z;
    __nv_bfloat16 *wp1, *wp2, *wp3;
    cudaGetSymbolAddress((void**)&agg1, g_agg1);
    cudaGetSymbolAddress((void**)&h1, g_h1);
    cudaGetSymbolAddress((void**)&h, g_h);
    cudaGetSymbolAddress((void**)&agg2, g_agg2);
    cudaGetSymbolAddress((void**)&z, g_z);
    cudaGetSymbolAddress((void**)&wp1, g_wp1);
    cudaGetSymbolAddress((void**)&wp2, g_wp2);
    cudaGetSymbolAddress((void**)&wp3, g_wp3);

    cudaFuncSetAttribute(gemm_mma<4>,
                         cudaFuncAttributeMaxDynamicSharedMemorySize,
                         SMEM_MMA_BYTES);
    cudaFuncSetAttribute(gemm_mma<8>,
                         cudaFuncAttributeMaxDynamicSharedMemorySize,
                         SMEM_MMA_BYTES);

    // index conversion + weight prep
    convert_kernel<<<(N_EDGES + 255) / 256, 256>>>(ei);
    prep_w_kernel<<<(128 * 256) / 256, 256>>>(W1a, wp1, 128);
    prep_w_kernel<<<(256 * 256) / 256, 256>>>(W1b, wp2, 256);
    prep_w_kernel<<<(256 * 256) / 256, 256>>>(W2a, wp3, 256);

    const dim3 tg((N_NODES + 127) / 128, 2);

    // ---- layer 1 ----
    {
        int n4 = N_NODES * FEAT / 4;
        copy4_kernel<<<(n4 + 255) / 256, 256>>>((float4*)agg1,
                                                (const float4*)x, n4);
        int nt = N_EDGES * (FEAT / 4);
        edge_agg_kernel<FEAT><<<(nt + 255) / 256, 256>>>(x, agg1);
        gemm_mma<4><<<tg, 512, SMEM_MMA_BYTES>>>(agg1, wp1, b1a, h1, N_NODES);
        gemm_mma<8><<<tg, 512, SMEM_MMA_BYTES>>>(h1, wp2, b1b, h, N_NODES);
    }
    // ---- layer 2 ----
    {
        int n4 = N_NODES * HID / 4;
        copy4_kernel<<<(n4 + 255) / 256, 256>>>((float4*)agg2,
                                                (const float4*)h, n4);
        int nt = N_EDGES * (HID / 4);
        edge_agg_kernel<HID><<<(nt + 255) / 256, 256>>>(h, agg2);
        gemm_mma<8><<<tg, 512, SMEM_MMA_BYTES>>>(agg2, wp3, b2a, z, N_NODES);
        gemm_out_k<<<(N_NODES + 7) / 8, 256>>>(z, W2b, b2b, out);
    }
}

// round 7
// speedup vs baseline: 2.0129x; 1.2971x over previous
#include <cuda_runtime.h>
#include <cuda_bf16.h>
#include <cstdint>

#define N_NODES 100000
#define N_EDGES 640000
#define FEAT 128
#define HID 256
#define NCLS 10

// ---------------------------------------------------------------------------
// Persistent scratch (re-initialized every launch before use).
// ---------------------------------------------------------------------------
__device__ __align__(16) float g_agg1[N_NODES * FEAT];
__device__ __align__(16) float g_h1[N_NODES * HID];
__device__ __align__(16) float g_h[N_NODES * HID];
__device__ __align__(16) float g_agg2[N_NODES * HID];
__device__ __align__(16) float g_z[N_NODES * HID];
__device__ int g_src[N_EDGES];
__device__ int g_dst[N_EDGES];
__device__ int g_ssrc[N_EDGES];     // src sorted by dst
__device__ int g_cnt[N_NODES];      // per-dst degree
__device__ int g_off[N_NODES + 1];  // CSR offsets
__device__ int g_cur[N_NODES];      // scatter cursors
__device__ int g_bsum[128];         // scan block sums
// prepped weights, bf16: [chunk][plane(hi,lo)][k(32)][n(256)]
__device__ __align__(16) __nv_bfloat16 g_wp1[4 * 2 * 32 * 256];  // W1a K=128
__device__ __align__(16) __nv_bfloat16 g_wp2[8 * 2 * 32 * 256];  // W1b K=256
__device__ __align__(16) __nv_bfloat16 g_wp3[8 * 2 * 32 * 256];  // W2a K=256

// ---------------------------------------------------------------------------
// mma.sync helpers (legacy tensor-core path; valid at compute_100)
// ---------------------------------------------------------------------------
#define LDSM4(r, a)                                                           \
    asm volatile("ldmatrix.sync.aligned.m8n8.x4.shared.b16 {%0,%1,%2,%3}, [%4];" \
                 : "=r"((r)[0]), "=r"((r)[1]), "=r"((r)[2]), "=r"((r)[3])     \
                 : "r"(a))
#define LDSM2T(r, a)                                                          \
    asm volatile("ldmatrix.sync.aligned.m8n8.x2.trans.shared.b16 {%0,%1}, [%2];" \
                 : "=r"((r)[0]), "=r"((r)[1])                                 \
                 : "r"(a))
#define MMA16816(c, A, B)                                                     \
    asm volatile(                                                             \
        "mma.sync.aligned.m16n8k16.row.col.f32.bf16.bf16.f32 "                \
        "{%0,%1,%2,%3},{%4,%5,%6,%7},{%8,%9},{%0,%1,%2,%3};"                  \
        : "+f"((c)[0]), "+f"((c)[1]), "+f"((c)[2]), "+f"((c)[3])              \
        : "r"((A)[0]), "r"((A)[1]), "r"((A)[2]), "r"((A)[3]), "r"((B)[0]),    \
          "r"((B)[1]))
#define CP_ASYNC16(dst, src)                                                  \
    asm volatile("cp.async.cg.shared.global [%0], [%1], 16;" ::"r"(dst),      \
                 "l"(src) : "memory")
#define CP_COMMIT() asm volatile("cp.async.commit_group;" ::: "memory")
#define CP_WAIT0() asm volatile("cp.async.wait_group 0;" ::: "memory")

__device__ __forceinline__ uint32_t smem_u32(const void* p) {
    uint32_t a;
    asm("{ .reg .u64 t; cvta.to.shared.u64 t, %1; cvt.u32.u64 %0, t; }"
        : "=r"(a) : "l"(p));
    return a;
}
// pack two floats to bf16x2 (lo -> low 16 bits)
__device__ __forceinline__ uint32_t pk(float lo, float hi) {
    uint32_t r;
    asm("cvt.rn.bf16x2.f32 %0, %1, %2;" : "=r"(r) : "f"(hi), "f"(lo));
    return r;
}
__device__ __forceinline__ float bfr(float x) {
    return __bfloat162float(__float2bfloat16(x));
}

// ---------------------------------------------------------------------------
// CSR build: zero bins -> convert+histogram -> scan (3 kernels) -> scatter
// ---------------------------------------------------------------------------
__global__ void zero_cnt_kernel() {
    int i = blockIdx.x * 256 + threadIdx.x;
    if (i < N_NODES) g_cnt[i] = 0;
}

// Edge-index conversion with per-block dtype sniff (JAX may demote
// int64->int32): genuine int64 of values < 2^31 has 0 in every odd 32-bit
// word of the first 256 slots; int32 random data cannot (p ~ 1e-1280).
__global__ void convert_hist_kernel(const void* __restrict__ ei) {
    __shared__ int s_is64;
    if (threadIdx.x == 0) {
        const unsigned int* w = (const unsigned int*)ei;
        int is64 = 1;
        for (int i = 0; i < 256; i++)
            if (w[2 * i + 1] != 0u) { is64 = 0; break; }
        s_is64 = is64;
    }
    __syncthreads();
    int e = blockIdx.x * 256 + threadIdx.x;
    if (e >= N_EDGES) return;
    int s, d;
    if (s_is64) {
        const long long* p = (const long long*)ei;
        s = (int)p[e];
        d = (int)p[N_EDGES + e];
    } else {
        const int* p = (const int*)ei;
        s = p[e];
        d = p[N_EDGES + e];
    }
    s = min(max(s, 0), N_NODES - 1);
    d = min(max(d, 0), N_NODES - 1);
    g_src[e] = s;
    g_dst[e] = d;
    atomicAdd(&g_cnt[d], 1);
}

// scan step 1: per-block (1024 elems) exclusive scan + block sums
__global__ void scan1_kernel() {
    __shared__ int sh[1024];
    const int tid = threadIdx.x;
    int i = blockIdx.x * 1024 + tid;
    int v = (i < N_NODES) ? g_cnt[i] : 0;
    sh[tid] = v;
    __syncthreads();
#pragma unroll
    for (int o = 1; o < 1024; o <<= 1) {
        int t = (tid >= o) ? sh[tid - o] : 0;
        __syncthreads();
        sh[tid] += t;
        __syncthreads();
    }
    if (i < N_NODES) g_off[i] = sh[tid] - v;  // exclusive within block
    if (tid == 1023) g_bsum[blockIdx.x] = sh[1023];
}

// scan step 2: serial scan over block sums (<=98 entries)
__global__ void scan2_kernel(int nb) {
    if (threadIdx.x == 0 && blockIdx.x == 0) {
        int acc = 0;
        for (int i = 0; i < nb; i++) {
            int v = g_bsum[i];
            g_bsum[i] = acc;
            acc += v;
        }
    }
}

// scan step 3: add block prefix, init cursors, cap sentinel
__global__ void scan3_kernel() {
    int i = blockIdx.x * 1024 + threadIdx.x;
    if (i < N_NODES) {
        int v = g_off[i] + g_bsum[blockIdx.x];
        g_off[i] = v;
        g_cur[i] = v;
    }
    if (i == 0) g_off[N_NODES] = N_EDGES;
}

__global__ void scatter_kernel() {
    int e = blockIdx.x * 256 + threadIdx.x;
    if (e >= N_EDGES) return;
    int d = g_dst[e];
    int pos = atomicAdd(&g_cur[d], 1);
    g_ssrc[pos] = g_src[e];
}

// ---------------------------------------------------------------------------
// CSR aggregation: warp per node. acc = x[node] + sum_{j->node} x[src_j].
// Lanes hold the row (D/128 float4 each); row reads fully coalesced.
// ---------------------------------------------------------------------------
template <int D>
__global__ void agg_csr_kernel(const float* __restrict__ x,
                               float* __restrict__ agg) {
    const int node = blockIdx.x * 8 + (threadIdx.x >> 5);
    if (node >= N_NODES) return;
    const int lane = threadIdx.x & 31;
    constexpr int C = D / 4;       // float4 per row
    constexpr int R = C / 32;      // float4 per lane (1 or 2)
    const float4* x4 = reinterpret_cast<const float4*>(x);

    float4 acc[R];
#pragma unroll
    for (int j = 0; j < R; j++)
        acc[j] = x4[(size_t)node * C + j * 32 + lane];

    const int e0 = g_off[node];
    const int e1 = g_off[node + 1];
    for (int e = e0; e < e1; e++) {
        int s = g_ssrc[e];
#pragma unroll
        for (int j = 0; j < R; j++) {
            float4 v = x4[(size_t)s * C + j * 32 + lane];
            acc[j].x += v.x;
            acc[j].y += v.y;
            acc[j].z += v.z;
            acc[j].w += v.w;
        }
    }
    float4* a4 = reinterpret_cast<float4*>(agg);
#pragma unroll
    for (int j = 0; j < R; j++)
        a4[(size_t)node * C + j * 32 + lane] = acc[j];
}

// ---------------------------------------------------------------------------
// Weight prep: W[K,256] fp32 -> bf16 hi/lo planes, layout
// [chunk(K/32)][plane(2)][k(32)][n(256)]
// ---------------------------------------------------------------------------
__global__ void prep_w_kernel(const float* __restrict__ W,
                              __nv_bfloat16* __restrict__ out, int K) {
    int i = blockIdx.x * 256 + threadIdx.x;
    if (i >= K * 256) return;
    int k = i >> 8;
    int n = i & 255;
    float v = W[(size_t)k * 256 + n];
    __nv_bfloat16 hi = __float2bfloat16(v);
    __nv_bfloat16 lo = __float2bfloat16(v - __bfloat162float(hi));
    int chunk = k >> 5, kk = k & 31;
    size_t base = ((size_t)chunk * 2 * 32 + kk) * 256 + n;
    out[base] = hi;                    // plane 0
    out[base + (size_t)32 * 256] = lo; // plane 1
}

// ---------------------------------------------------------------------------
// bf16x3 mma.sync GEMM: C[M,256] = relu(A[M,K] @ W[K,256] + bias)
// CTA 128x128, 512 threads (16 warps, 4x4), warp tile 32x32, BK=32, 2 stages.
// SMEM per stage: A_hi[128][40bf16] | A_lo | B_hi[32][136bf16] | B_lo
// ---------------------------------------------------------------------------
#define A_HI_OFF 0
#define A_LO_OFF 10240
#define B_HI_OFF 20480
#define B_LO_OFF 29184
#define STAGE_BYTES 37888
#define SMEM_MMA_BYTES (2 * STAGE_BYTES)

template <int NC>  // K / 32
__global__ __launch_bounds__(512)
void gemm_mma(const float* __restrict__ A,
              const __nv_bfloat16* __restrict__ wp,
              const float* __restrict__ bias, float* __restrict__ C, int M) {
    extern __shared__ __align__(1024) char smem[];
    const uint32_t sb = smem_u32(smem);
    const int K = NC * 32;
    const int t = threadIdx.x;
    const int lane = t & 31;
    const int warp = t >> 5;
    const int warp_m = warp >> 2;  // 0..3 (32 rows each)
    const int warp_n = warp & 3;   // 0..3 (32 cols each)
    const int bm = blockIdx.x * 128;
    const int bn = blockIdx.y * 128;

    // ---- A fill coords: thread -> (row 0..127, q 0..3 of 8 floats) ----
    const int a_row = t >> 2;
    const int a_q = t & 3;
    const bool rok = (bm + a_row) < M;
    const float* Ag = A + (size_t)(bm + a_row) * K + a_q * 8;
    const uint32_t a_dst = sb + a_row * 80 + a_q * 16;

    // ---- B fill coords (two cp.async per thread, planes hi/lo) ----
    const int b_k = (t >> 4) & 31;
    const int b_seg = t & 15;

    // ---- ldmatrix per-thread offsets ----
    const int lm_arow = warp_m * 32 + (lane & 7) + ((lane >> 3) & 1) * 8;
    const uint32_t a_lm = sb + lm_arow * 80 + ((lane >> 4) & 1) * 16;
    const uint32_t b_lm = sb + B_HI_OFF + (lane & 15) * 272 + warp_n * 64;

    float acc[2][4][4];
#pragma unroll
    for (int i = 0; i < 2; i++)
#pragma unroll
        for (int j = 0; j < 4; j++)
#pragma unroll
            for (int k = 0; k < 4; k++) acc[i][j][k] = 0.f;

    // ---- helpers ----
    auto fill_B = [&](int c, int stg) {
        const __nv_bfloat16* srcH =
            wp + (((size_t)c * 2 + 0) * 32 + b_k) * 256 + bn + b_seg * 8;
        const __nv_bfloat16* srcL =
            wp + (((size_t)c * 2 + 1) * 32 + b_k) * 256 + bn + b_seg * 8;
        uint32_t dstH =
            sb + stg * STAGE_BYTES + B_HI_OFF + b_k * 272 + b_seg * 16;
        uint32_t dstL =
            sb + stg * STAGE_BYTES + B_LO_OFF + b_k * 272 + b_seg * 16;
        CP_ASYNC16(dstH, (const void*)srcH);
        CP_ASYNC16(dstL, (const void*)srcL);
        CP_COMMIT();
    };
    auto store_A = [&](int stg, float4 v0, float4 v1) {
        uint32_t h0 = pk(v0.x, v0.y), h1 = pk(v0.z, v0.w);
        uint32_t h2 = pk(v1.x, v1.y), h3 = pk(v1.z, v1.w);
        uint32_t l0 = pk(v0.x - bfr(v0.x), v0.y - bfr(v0.y));
        uint32_t l1 = pk(v0.z - bfr(v0.z), v0.w - bfr(v0.w));
        uint32_t l2 = pk(v1.x - bfr(v1.x), v1.y - bfr(v1.y));
        uint32_t l3 = pk(v1.z - bfr(v1.z), v1.w - bfr(v1.w));
        uint32_t d = a_dst + stg * STAGE_BYTES;
        asm volatile("st.shared.v4.b32 [%0], {%1,%2,%3,%4};" ::"r"(d), "r"(h0),
                     "r"(h1), "r"(h2), "r"(h3));
        asm volatile("st.shared.v4.b32 [%0], {%1,%2,%3,%4};" ::"r"(
                         d + A_LO_OFF),
                     "r"(l0), "r"(l1), "r"(l2), "r"(l3));
    };
    auto load_A = [&](int c, float4& v0, float4& v1) {
        if (rok) {
            v0 = *reinterpret_cast<const float4*>(Ag + c * 32);
            v1 = *reinterpret_cast<const float4*>(Ag + c * 32 + 4);
        } else {
            v0 = make_float4(0.f, 0.f, 0.f, 0.f);
            v1 = v0;
        }
    };
    auto compute = [&](int stg) {
        const uint32_t abase = a_lm + stg * STAGE_BYTES;
        const uint32_t bbase = b_lm + stg * STAGE_BYTES;
#pragma unroll
        for (int ks = 0; ks < 2; ks++) {
            uint32_t Ah[2][4], Al[2][4], Bh[4][2], Bl[4][2];
#pragma unroll
            for (int mt = 0; mt < 2; mt++) {
                uint32_t ad = abase + mt * (16 * 80) + ks * 32;
                LDSM4(Ah[mt], ad);
                LDSM4(Al[mt], ad + A_LO_OFF);
            }
#pragma unroll
            for (int nt = 0; nt < 4; nt++) {
                uint32_t bd = bbase + ks * (16 * 272) + nt * 16;
                LDSM2T(Bh[nt], bd);
                LDSM2T(Bl[nt], bd + (B_LO_OFF - B_HI_OFF));
            }
#pragma unroll
            for (int mt = 0; mt < 2; mt++)
#pragma unroll
                for (int nt = 0; nt < 4; nt++) {
                    MMA16816(acc[mt][nt], Ah[mt], Bh[nt]);
                    MMA16816(acc[mt][nt], Al[mt], Bh[nt]);
                    MMA16816(acc[mt][nt], Ah[mt], Bl[nt]);
                }
        }
    };

    // ---- prologue ----
    {
        fill_B(0, 0);
        float4 v0, v1;
        load_A(0, v0, v1);
        store_A(0, v0, v1);
        CP_WAIT0();
        __syncthreads();
    }
    // ---- main loop ----
    for (int c = 0; c < NC; c++) {
        const int s = c & 1;
        const bool nxt = (c + 1 < NC);
        float4 v0, v1;
        if (nxt) {
            fill_B(c + 1, s ^ 1);
            load_A(c + 1, v0, v1);
        }
        compute(s);
        if (nxt) {
            store_A(s ^ 1, v0, v1);
            CP_WAIT0();
            __syncthreads();
        }
    }

    // ---- epilogue: bias + relu, float2 stores ----
#pragma unroll
    for (int mt = 0; mt < 2; mt++) {
        int r0 = bm + warp_m * 32 + mt * 16 + (lane >> 2);
#pragma unroll
        for (int nt = 0; nt < 4; nt++) {
            int col = bn + warp_n * 32 + nt * 8 + (lane & 3) * 2;
            float b0 = bias[col], b1 = bias[col + 1];
            if (r0 < M) {
                float2 o;
                o.x = fmaxf(acc[mt][nt][0] + b0, 0.f);
                o.y = fmaxf(acc[mt][nt][1] + b1, 0.f);
                *reinterpret_cast<float2*>(C + (size_t)r0 * HID + col) = o;
            }
            if (r0 + 8 < M) {
                float2 o;
                o.x = fmaxf(acc[mt][nt][2] + b0, 0.f);
                o.y = fmaxf(acc[mt][nt][3] + b1, 0.f);
                *reinterpret_cast<float2*>(C + (size_t)(r0 + 8) * HID + col) = o;
            }
        }
    }
}

// ---------------------------------------------------------------------------
// Final GEMM: out[M,10] = Z[M,256] @ W[256,10] + b.
// ---------------------------------------------------------------------------
__global__ void gemm_out_k(const float* __restrict__ Z,
                           const float* __restrict__ W,
                           const float* __restrict__ bias,
                           float* __restrict__ out) {
    __shared__ float Ws[NCLS][HID];
    __shared__ float bs[NCLS];
    const int t = threadIdx.x;
    for (int i = t; i < HID * NCLS; i += 256) {
        int k = i / NCLS;
        int c = i - k * NCLS;
        Ws[c][k] = W[i];
    }
    if (t < NCLS) bs[t] = bias[t];
    __syncthreads();

    const int lane = t & 31;
    const int row = blockIdx.x * 8 + (t >> 5);
    if (row >= N_NODES) return;

    const float* zr = Z + (size_t)row * HID;
    float zv[8];
#pragma unroll
    for (int i = 0; i < 8; i++) zv[i] = zr[i * 32 + lane];

#pragma unroll
    for (int c = 0; c < NCLS; c++) {
        float s = 0.f;
#pragma unroll
        for (int i = 0; i < 8; i++) s += zv[i] * Ws[c][i * 32 + lane];
#pragma unroll
        for (int o = 16; o > 0; o >>= 1) s += __shfl_xor_sync(0xffffffffu, s, o);
        if (lane == 0) out[row * NCLS + c] = s + bs[c];
    }
}

// ---------------------------------------------------------------------------
// Launch sequence (default stream; graph-capturable, alloc-free)
// ---------------------------------------------------------------------------
extern "C" void kernel_launch(void* const* d_in, const int* in_sizes, int n_in,
                              void* d_out, int out_size) {
    (void)in_sizes; (void)n_in; (void)out_size;
    const float* x = (const float*)d_in[0];
    const void* ei = d_in[1];
    const float* W1a = (const float*)d_in[2];
    const float* b1a = (const float*)d_in[3];
    const float* W1b = (const float*)d_in[4];
    const float* b1b = (const float*)d_in[5];
    const float* W2a = (const float*)d_in[6];
    const float* b2a = (const float*)d_in[7];
    const float* W2b = (const float*)d_in[8];
    const float* b2b = (const float*)d_in[9];
    float* out = (float*)d_out;

    float *agg1, *h1, *h, *agg2, *z;
    __nv_bfloat16 *wp1, *wp2, *wp3;
    cudaGetSymbolAddress((void**)&agg1, g_agg1);
    cudaGetSymbolAddress((void**)&h1, g_h1);
    cudaGetSymbolAddress((void**)&h, g_h);
    cudaGetSymbolAddress((void**)&agg2, g_agg2);
    cudaGetSymbolAddress((void**)&z, g_z);
    cudaGetSymbolAddress((void**)&wp1, g_wp1);
    cudaGetSymbolAddress((void**)&wp2, g_wp2);
    cudaGetSymbolAddress((void**)&wp3, g_wp3);

    cudaFuncSetAttribute(gemm_mma<4>,
                         cudaFuncAttributeMaxDynamicSharedMemorySize,
                         SMEM_MMA_BYTES);
    cudaFuncSetAttribute(gemm_mma<8>,
                         cudaFuncAttributeMaxDynamicSharedMemorySize,
                         SMEM_MMA_BYTES);

    // ---- CSR build ----
    const int scan_blocks = (N_NODES + 1023) / 1024;  // 98
    zero_cnt_kernel<<<(N_NODES + 255) / 256, 256>>>();
    convert_hist_kernel<<<(N_EDGES + 255) / 256, 256>>>(ei);
    scan1_kernel<<<scan_blocks, 1024>>>();
    scan2_kernel<<<1, 32>>>(scan_blocks);
    scan3_kernel<<<scan_blocks, 1024>>>();
    scatter_kernel<<<(N_EDGES + 255) / 256, 256>>>();

    // ---- weight prep ----
    prep_w_kernel<<<(128 * 256) / 256, 256>>>(W1a, wp1, 128);
    prep_w_kernel<<<(256 * 256) / 256, 256>>>(W1b, wp2, 256);
    prep_w_kernel<<<(256 * 256) / 256, 256>>>(W2a, wp3, 256);

    const dim3 tg((N_NODES + 127) / 128, 2);
    const int agg_blocks = (N_NODES + 7) / 8;

    // ---- layer 1 ----
    agg_csr_kernel<FEAT><<<agg_blocks, 256>>>(x, agg1);
    gemm_mma<4><<<tg, 512, SMEM_MMA_BYTES>>>(agg1, wp1, b1a, h1, N_NODES);
    gemm_mma<8><<<tg, 512, SMEM_MMA_BYTES>>>(h1, wp2, b1b, h, N_NODES);
    // ---- layer 2 ----
    agg_csr_kernel<HID><<<agg_blocks, 256>>>(h, agg2);
    gemm_mma<8><<<tg, 512, SMEM_MMA_BYTES>>>(agg2, wp3, b2a, z, N_NODES);
    gemm_out_k<<<(N_NODES + 7) / 8, 256>>>(z, W2b, b2b, out);
}

// round 8
// speedup vs baseline: 2.0877x; 1.0372x over previous
#include <cuda_runtime.h>
#include <cuda_bf16.h>
#include <cstdint>

#define N_NODES 100000
#define N_EDGES 640000
#define FEAT 128
#define HID 256
#define NCLS 10

// ---------------------------------------------------------------------------
// Persistent scratch (re-initialized every launch before use).
// ---------------------------------------------------------------------------
__device__ __align__(16) float g_agg1[N_NODES * FEAT];
__device__ __align__(16) float g_h1[N_NODES * HID];
__device__ __align__(16) float g_h[N_NODES * HID];
__device__ __align__(16) float g_agg2[N_NODES * HID];
__device__ __align__(16) float g_z[N_NODES * HID];
__device__ int g_src[N_EDGES];
__device__ int g_dst[N_EDGES];
__device__ int g_ssrc[N_EDGES];     // src sorted by dst
__device__ int g_cnt[N_NODES];      // per-dst degree
__device__ int g_off[N_NODES + 1];  // CSR offsets
__device__ int g_cur[N_NODES];      // scatter cursors
__device__ int g_bsum[128];         // scan block sums
// prepped weights, bf16: [chunk][plane(hi,lo)][k(32)][n(256)]
__device__ __align__(16) __nv_bfloat16 g_wp1[4 * 2 * 32 * 256];  // W1a K=128
__device__ __align__(16) __nv_bfloat16 g_wp2[8 * 2 * 32 * 256];  // W1b K=256
__device__ __align__(16) __nv_bfloat16 g_wp3[8 * 2 * 32 * 256];  // W2a K=256

// ---------------------------------------------------------------------------
// mma.sync helpers (legacy tensor-core path; valid at compute_100)
// ---------------------------------------------------------------------------
#define LDSM4(r, a)                                                           \
    asm volatile("ldmatrix.sync.aligned.m8n8.x4.shared.b16 {%0,%1,%2,%3}, [%4];" \
                 : "=r"((r)[0]), "=r"((r)[1]), "=r"((r)[2]), "=r"((r)[3])     \
                 : "r"(a))
#define LDSM2T(r, a)                                                          \
    asm volatile("ldmatrix.sync.aligned.m8n8.x2.trans.shared.b16 {%0,%1}, [%2];" \
                 : "=r"((r)[0]), "=r"((r)[1])                                 \
                 : "r"(a))
#define MMA16816(c, A, B)                                                     \
    asm volatile(                                                             \
        "mma.sync.aligned.m16n8k16.row.col.f32.bf16.bf16.f32 "                \
        "{%0,%1,%2,%3},{%4,%5,%6,%7},{%8,%9},{%0,%1,%2,%3};"                  \
        : "+f"((c)[0]), "+f"((c)[1]), "+f"((c)[2]), "+f"((c)[3])              \
        : "r"((A)[0]), "r"((A)[1]), "r"((A)[2]), "r"((A)[3]), "r"((B)[0]),    \
          "r"((B)[1]))
#define CP_ASYNC16(dst, src)                                                  \
    asm volatile("cp.async.cg.shared.global [%0], [%1], 16;" ::"r"(dst),      \
                 "l"(src) : "memory")
#define CP_COMMIT() asm volatile("cp.async.commit_group;" ::: "memory")
#define CP_WAIT0() asm volatile("cp.async.wait_group 0;" ::: "memory")

__device__ __forceinline__ uint32_t smem_u32(const void* p) {
    uint32_t a;
    asm("{ .reg .u64 t; cvta.to.shared.u64 t, %1; cvt.u32.u64 %0, t; }"
        : "=r"(a) : "l"(p));
    return a;
}
// pack two floats to bf16x2 (lo -> low 16 bits)
__device__ __forceinline__ uint32_t pk(float lo, float hi) {
    uint32_t r;
    asm("cvt.rn.bf16x2.f32 %0, %1, %2;" : "=r"(r) : "f"(hi), "f"(lo));
    return r;
}
__device__ __forceinline__ float bfr(float x) {
    return __bfloat162float(__float2bfloat16(x));
}

// ---------------------------------------------------------------------------
// Fused setup: weight prep (3 matrices) + zero histogram bins.
// Weight layout: [chunk(K/32)][plane(hi,lo)][k(32)][n(256)]
// ---------------------------------------------------------------------------
__device__ __forceinline__ void prep_one(const float* __restrict__ W,
                                         __nv_bfloat16* __restrict__ out,
                                         int i) {
    int k = i >> 8;
    int n = i & 255;
    float v = W[(size_t)k * 256 + n];
    __nv_bfloat16 hi = __float2bfloat16(v);
    __nv_bfloat16 lo = __float2bfloat16(v - __bfloat162float(hi));
    int chunk = k >> 5, kk = k & 31;
    size_t base = ((size_t)chunk * 2 * 32 + kk) * 256 + n;
    out[base] = hi;
    out[base + (size_t)32 * 256] = lo;
}

__global__ void setup_kernel(const float* __restrict__ W1a,
                             const float* __restrict__ W1b,
                             const float* __restrict__ W2a,
                             __nv_bfloat16* __restrict__ wp1,
                             __nv_bfloat16* __restrict__ wp2,
                             __nv_bfloat16* __restrict__ wp3) {
    int i = blockIdx.x * 256 + threadIdx.x;
    if (i < 128 * 256) prep_one(W1a, wp1, i);
    if (i < 256 * 256) {
        prep_one(W1b, wp2, i);
        prep_one(W2a, wp3, i);
    }
    if (i < N_NODES) g_cnt[i] = 0;
}

// ---------------------------------------------------------------------------
// Edge-index conversion + histogram with per-block dtype sniff (JAX may
// demote int64->int32): genuine int64 of values < 2^31 has 0 in every odd
// 32-bit word of the first 256 slots; int32 random data cannot (p~1e-1280).
// ---------------------------------------------------------------------------
__global__ void convert_hist_kernel(const void* __restrict__ ei) {
    __shared__ int s_is64;
    if (threadIdx.x == 0) {
        const unsigned int* w = (const unsigned int*)ei;
        int is64 = 1;
        for (int i = 0; i < 256; i++)
            if (w[2 * i + 1] != 0u) { is64 = 0; break; }
        s_is64 = is64;
    }
    __syncthreads();
    int e = blockIdx.x * 256 + threadIdx.x;
    if (e >= N_EDGES) return;
    int s, d;
    if (s_is64) {
        const long long* p = (const long long*)ei;
        s = (int)p[e];
        d = (int)p[N_EDGES + e];
    } else {
        const int* p = (const int*)ei;
        s = p[e];
        d = p[N_EDGES + e];
    }
    s = min(max(s, 0), N_NODES - 1);
    d = min(max(d, 0), N_NODES - 1);
    g_src[e] = s;
    g_dst[e] = d;
    atomicAdd(&g_cnt[d], 1);
}

// scan step 1: per-block (1024 elems) exclusive scan + block sums
__global__ void scan1_kernel() {
    __shared__ int sh[1024];
    const int tid = threadIdx.x;
    int i = blockIdx.x * 1024 + tid;
    int v = (i < N_NODES) ? g_cnt[i] : 0;
    sh[tid] = v;
    __syncthreads();
#pragma unroll
    for (int o = 1; o < 1024; o <<= 1) {
        int t = (tid >= o) ? sh[tid - o] : 0;
        __syncthreads();
        sh[tid] += t;
        __syncthreads();
    }
    if (i < N_NODES) g_off[i] = sh[tid] - v;  // exclusive within block
    if (tid == 1023) g_bsum[blockIdx.x] = sh[1023];
}

// scan step 2: exclusive scan over block sums (<=128 entries), one block
__global__ void scan2_kernel(int nb) {
    __shared__ int sh[128];
    const int tid = threadIdx.x;
    int v = (tid < nb) ? g_bsum[tid] : 0;
    sh[tid] = v;
    __syncthreads();
#pragma unroll
    for (int o = 1; o < 128; o <<= 1) {
        int t = (tid >= o) ? sh[tid - o] : 0;
        __syncthreads();
        sh[tid] += t;
        __syncthreads();
    }
    if (tid < nb) g_bsum[tid] = sh[tid] - v;  // exclusive
}

// scan step 3: add block prefix, init cursors, cap sentinel
__global__ void scan3_kernel() {
    int i = blockIdx.x * 1024 + threadIdx.x;
    if (i < N_NODES) {
        int v = g_off[i] + g_bsum[blockIdx.x];
        g_off[i] = v;
        g_cur[i] = v;
    }
    if (i == 0) g_off[N_NODES] = N_EDGES;
}

__global__ void scatter_kernel() {
    int e = blockIdx.x * 256 + threadIdx.x;
    if (e >= N_EDGES) return;
    int d = g_dst[e];
    int pos = atomicAdd(&g_cur[d], 1);
    g_ssrc[pos] = g_src[e];
}

// ---------------------------------------------------------------------------
// CSR aggregation: warp per node. acc = x[node] + sum_{j->node} x[src_j].
// ---------------------------------------------------------------------------
template <int D>
__global__ void agg_csr_kernel(const float* __restrict__ x,
                               float* __restrict__ agg) {
    const int node = blockIdx.x * 8 + (threadIdx.x >> 5);
    if (node >= N_NODES) return;
    const int lane = threadIdx.x & 31;
    constexpr int C = D / 4;
    constexpr int R = C / 32;
    const float4* x4 = reinterpret_cast<const float4*>(x);

    float4 acc[R];
#pragma unroll
    for (int j = 0; j < R; j++)
        acc[j] = x4[(size_t)node * C + j * 32 + lane];

    const int e0 = g_off[node];
    const int e1 = g_off[node + 1];
    for (int e = e0; e < e1; e++) {
        int s = g_ssrc[e];
#pragma unroll
        for (int j = 0; j < R; j++) {
            float4 v = x4[(size_t)s * C + j * 32 + lane];
            acc[j].x += v.x;
            acc[j].y += v.y;
            acc[j].z += v.z;
            acc[j].w += v.w;
        }
    }
    float4* a4 = reinterpret_cast<float4*>(agg);
#pragma unroll
    for (int j = 0; j < R; j++)
        a4[(size_t)node * C + j * 32 + lane] = acc[j];
}

// ---------------------------------------------------------------------------
// bf16x3 mma.sync GEMM, full-width tile: C[M,256] = relu(A[M,K]@W[K,256]+b)
// CTA 128x256, 512 threads (16 warps: 4m x 4n), warp tile 32x64, BK=32,
// 2 stages. SMEM/stage: A_hi[128][40bf16] | A_lo | B_hi[32][264bf16] | B_lo
// ---------------------------------------------------------------------------
#define A_HI_OFF 0
#define A_LO_OFF 10240
#define B_HI_OFF 20480
#define B_LO_OFF 37376                 // B_HI + 32*528
#define STAGE_BYTES 54272              // B_LO + 32*528
#define SMEM_MMA_BYTES (2 * STAGE_BYTES)

template <int NC>  // K / 32
__global__ __launch_bounds__(512)
void gemm_mma(const float* __restrict__ A,
              const __nv_bfloat16* __restrict__ wp,
              const float* __restrict__ bias, float* __restrict__ C, int M) {
    extern __shared__ __align__(1024) char smem[];
    const uint32_t sb = smem_u32(smem);
    const int K = NC * 32;
    const int t = threadIdx.x;
    const int lane = t & 31;
    const int warp = t >> 5;
    const int warp_m = warp >> 2;  // 0..3 (32 rows each)
    const int warp_n = warp & 3;   // 0..3 (64 cols each)
    const int bm = blockIdx.x * 128;

    // ---- A fill coords: thread -> (row 0..127, q 0..3 of 8 floats) ----
    const int a_row = t >> 2;
    const int a_q = t & 3;
    const bool rok = (bm + a_row) < M;
    const float* Ag = A + (size_t)(bm + a_row) * K + a_q * 8;
    const uint32_t a_dst = sb + a_row * 80 + a_q * 16;

    // ---- ldmatrix per-thread offsets ----
    const int lm_arow = warp_m * 32 + (lane & 7) + ((lane >> 3) & 1) * 8;
    const uint32_t a_lm = sb + lm_arow * 80 + ((lane >> 4) & 1) * 16;
    const uint32_t b_lm = sb + B_HI_OFF + (lane & 15) * 528 + warp_n * 128;

    float acc[2][8][4];
#pragma unroll
    for (int i = 0; i < 2; i++)
#pragma unroll
        for (int j = 0; j < 8; j++)
#pragma unroll
            for (int k = 0; k < 4; k++) acc[i][j][k] = 0.f;

    // ---- helpers ----
    auto fill_B = [&](int c, int stg) {
        // 2 planes x 32 k-rows x 512B = 2048 x 16B chunks; 4 per thread
#pragma unroll
        for (int i = 0; i < 4; i++) {
            int f = t + i * 512;
            int pl = f >> 10;
            int k = (f >> 5) & 31;
            int seg = f & 31;
            const __nv_bfloat16* src =
                wp + (((size_t)c * 2 + pl) * 32 + k) * 256 + seg * 8;
            uint32_t dst = sb + stg * STAGE_BYTES +
                           (pl ? B_LO_OFF : B_HI_OFF) + k * 528 + seg * 16;
            CP_ASYNC16(dst, (const void*)src);
        }
        CP_COMMIT();
    };
    auto store_A = [&](int stg, float4 v0, float4 v1) {
        uint32_t h0 = pk(v0.x, v0.y), h1 = pk(v0.z, v0.w);
        uint32_t h2 = pk(v1.x, v1.y), h3 = pk(v1.z, v1.w);
        uint32_t l0 = pk(v0.x - bfr(v0.x), v0.y - bfr(v0.y));
        uint32_t l1 = pk(v0.z - bfr(v0.z), v0.w - bfr(v0.w));
        uint32_t l2 = pk(v1.x - bfr(v1.x), v1.y - bfr(v1.y));
        uint32_t l3 = pk(v1.z - bfr(v1.z), v1.w - bfr(v1.w));
        uint32_t d = a_dst + stg * STAGE_BYTES;
        asm volatile("st.shared.v4.b32 [%0], {%1,%2,%3,%4};" ::"r"(d), "r"(h0),
                     "r"(h1), "r"(h2), "r"(h3));
        asm volatile("st.shared.v4.b32 [%0], {%1,%2,%3,%4};" ::"r"(
                         d + A_LO_OFF),
                     "r"(l0), "r"(l1), "r"(l2), "r"(l3));
    };
    auto load_A = [&](int c, float4& v0, float4& v1) {
        if (rok) {
            v0 = *reinterpret_cast<const float4*>(Ag + c * 32);
            v1 = *reinterpret_cast<const float4*>(Ag + c * 32 + 4);
        } else {
            v0 = make_float4(0.f, 0.f, 0.f, 0.f);
            v1 = v0;
        }
    };
    auto compute = [&](int stg) {
        const uint32_t abase = a_lm + stg * STAGE_BYTES;
        const uint32_t bbase = b_lm + stg * STAGE_BYTES;
#pragma unroll
        for (int ks = 0; ks < 2; ks++) {
            uint32_t Ah[2][4], Al[2][4], Bh[8][2], Bl[8][2];
#pragma unroll
            for (int mt = 0; mt < 2; mt++) {
                uint32_t ad = abase + mt * (16 * 80) + ks * 32;
                LDSM4(Ah[mt], ad);
                LDSM4(Al[mt], ad + A_LO_OFF);
            }
#pragma unroll
            for (int nt = 0; nt < 8; nt++) {
                uint32_t bd = bbase + ks * (16 * 528) + nt * 16;
                LDSM2T(Bh[nt], bd);
                LDSM2T(Bl[nt], bd + (B_LO_OFF - B_HI_OFF));
            }
#pragma unroll
            for (int mt = 0; mt < 2; mt++)
#pragma unroll
                for (int nt = 0; nt < 8; nt++) {
                    MMA16816(acc[mt][nt], Ah[mt], Bh[nt]);
                    MMA16816(acc[mt][nt], Al[mt], Bh[nt]);
                    MMA16816(acc[mt][nt], Ah[mt], Bl[nt]);
                }
        }
    };

    // ---- prologue ----
    {
        fill_B(0, 0);
        float4 v0, v1;
        load_A(0, v0, v1);
        store_A(0, v0, v1);
        CP_WAIT0();
        __syncthreads();
    }
    // ---- main loop ----
    for (int c = 0; c < NC; c++) {
        const int s = c & 1;
        const bool nxt = (c + 1 < NC);
        float4 v0, v1;
        if (nxt) {
            fill_B(c + 1, s ^ 1);
            load_A(c + 1, v0, v1);
        }
        compute(s);
        if (nxt) {
            store_A(s ^ 1, v0, v1);
            CP_WAIT0();
            __syncthreads();
        }
    }

    // ---- epilogue: bias + relu, float2 stores ----
#pragma unroll
    for (int mt = 0; mt < 2; mt++) {
        int r0 = bm + warp_m * 32 + mt * 16 + (lane >> 2);
#pragma unroll
        for (int nt = 0; nt < 8; nt++) {
            int col = warp_n * 64 + nt * 8 + (lane & 3) * 2;
            float b0 = bias[col], b1 = bias[col + 1];
            if (r0 < M) {
                float2 o;
                o.x = fmaxf(acc[mt][nt][0] + b0, 0.f);
                o.y = fmaxf(acc[mt][nt][1] + b1, 0.f);
                *reinterpret_cast<float2*>(C + (size_t)r0 * HID + col) = o;
            }
            if (r0 + 8 < M) {
                float2 o;
                o.x = fmaxf(acc[mt][nt][2] + b0, 0.f);
                o.y = fmaxf(acc[mt][nt][3] + b1, 0.f);
                *reinterpret_cast<float2*>(C + (size_t)(r0 + 8) * HID + col) = o;
            }
        }
    }
}

// ---------------------------------------------------------------------------
// Final GEMM: out[M,10] = Z[M,256] @ W[256,10] + b.
// ---------------------------------------------------------------------------
__global__ void gemm_out_k(const float* __restrict__ Z,
                           const float* __restrict__ W,
                           const float* __restrict__ bias,
                           float* __restrict__ out) {
    __shared__ float Ws[NCLS][HID];
    __shared__ float bs[NCLS];
    const int t = threadIdx.x;
    for (int i = t; i < HID * NCLS; i += 256) {
        int k = i / NCLS;
        int c = i - k * NCLS;
        Ws[c][k] = W[i];
    }
    if (t < NCLS) bs[t] = bias[t];
    __syncthreads();

    const int lane = t & 31;
    const int row = blockIdx.x * 8 + (t >> 5);
    if (row >= N_NODES) return;

    const float* zr = Z + (size_t)row * HID;
    float zv[8];
#pragma unroll
    for (int i = 0; i < 8; i++) zv[i] = zr[i * 32 + lane];

#pragma unroll
    for (int c = 0; c < NCLS; c++) {
        float s = 0.f;
#pragma unroll
        for (int i = 0; i < 8; i++) s += zv[i] * Ws[c][i * 32 + lane];
#pragma unroll
        for (int o = 16; o > 0; o >>= 1) s += __shfl_xor_sync(0xffffffffu, s, o);
        if (lane == 0) out[row * NCLS + c] = s + bs[c];
    }
}

// ---------------------------------------------------------------------------
// Launch sequence (default stream; graph-capturable, alloc-free)
// ---------------------------------------------------------------------------
extern "C" void kernel_launch(void* const* d_in, const int* in_sizes, int n_in,
                              void* d_out, int out_size) {
    (void)in_sizes; (void)n_in; (void)out_size;
    const float* x = (const float*)d_in[0];
    const void* ei = d_in[1];
    const float* W1a = (const float*)d_in[2];
    const float* b1a = (const float*)d_in[3];
    const float* W1b = (const float*)d_in[4];
    const float* b1b = (const float*)d_in[5];
    const float* W2a = (const float*)d_in[6];
    const float* b2a = (const float*)d_in[7];
    const float* W2b = (const float*)d_in[8];
    const float* b2b = (const float*)d_in[9];
    float* out = (float*)d_out;

    float *agg1, *h1, *h, *agg2, *z;
    __nv_bfloat16 *wp1, *wp2, *wp3;
    cudaGetSymbolAddress((void**)&agg1, g_agg1);
    cudaGetSymbolAddress((void**)&h1, g_h1);
    cudaGetSymbolAddress((void**)&h, g_h);
    cudaGetSymbolAddress((void**)&agg2, g_agg2);
    cudaGetSymbolAddress((void**)&z, g_z);
    cudaGetSymbolAddress((void**)&wp1, g_wp1);
    cudaGetSymbolAddress((void**)&wp2, g_wp2);
    cudaGetSymbolAddress((void**)&wp3, g_wp3);

    cudaFuncSetAttribute(gemm_mma<4>,
                         cudaFuncAttributeMaxDynamicSharedMemorySize,
                         SMEM_MMA_BYTES);
    cudaFuncSetAttribute(gemm_mma<8>,
                         cudaFuncAttributeMaxDynamicSharedMemorySize,
                         SMEM_MMA_BYTES);

    // ---- setup (weight prep + bin zero) + CSR build ----
    const int scan_blocks = (N_NODES + 1023) / 1024;  // 98
    setup_kernel<<<(N_NODES + 255) / 256, 256>>>(W1a, W1b, W2a, wp1, wp2, wp3);
    convert_hist_kernel<<<(N_EDGES + 255) / 256, 256>>>(ei);
    scan1_kernel<<<scan_blocks, 1024>>>();
    scan2_kernel<<<1, 128>>>(scan_blocks);
    scan3_kernel<<<scan_blocks, 1024>>>();
    scatter_kernel<<<(N_EDGES + 255) / 256, 256>>>();

    const int tg = (N_NODES + 127) / 128;  // 782, full-width N=256 tiles
    const int agg_blocks = (N_NODES + 7) / 8;

    // ---- layer 1 ----
    agg_csr_kernel<FEAT><<<agg_blocks, 256>>>(x, agg1);
    gemm_mma<4><<<tg, 512, SMEM_MMA_BYTES>>>(agg1, wp1, b1a, h1, N_NODES);
    gemm_mma<8><<<tg, 512, SMEM_MMA_BYTES>>>(h1, wp2, b1b, h, N_NODES);
    // ---- layer 2 ----
    agg_csr_kernel<HID><<<agg_blocks, 256>>>(h, agg2);
    gemm_mma<8><<<tg, 512, SMEM_MMA_BYTES>>>(agg2, wp3, b2a, z, N_NODES);
    gemm_out_k<<<(N_NODES + 7) / 8, 256>>>(z, W2b, b2b, out);
}